// round 7
// baseline (speedup 1.0000x reference)
#include <cuda_runtime.h>
#include <cuda_bf16.h>

#define NN 100000
#define NE 1600000
#define NPB 32            // nodes per block in layer kernel
#define LTH 128           // threads per layer block

// ---------------- scratch (no allocations allowed; device-side refs ONLY) ----------------
__device__ int   g_deg[NN];
__device__ int   g_off[NN + 1];
__device__ int   g_cur[NN];
__device__ int   g_srcs[NE];         // src ids grouped by dst (CSR adjacency)
__device__ float g_h1[NN * 64];      // relu(layer0 out)
__device__ float g_h2[NN * 64];      // relu(layer1 out)

// ---------------- CSR build ----------------
__global__ void zero_deg_kernel() {
    int i = blockIdx.x * blockDim.x + threadIdx.x;
    if (i < NN) g_deg[i] = 0;
}

__global__ void count_deg_kernel(const int* __restrict__ ei) {
    int e = blockIdx.x * blockDim.x + threadIdx.x;
    if (e < NE) {
        int d = ei[NE + e];   // dst row (int32 on device; jax x64 is off)
        d = min(max(d, 0), NN - 1);
        atomicAdd(&g_deg[d], 1);
    }
}

// single-block exclusive scan of g_deg -> g_off, g_cur
__global__ void scan_deg_kernel() {
    __shared__ int part[1024];
    const int CH = (NN + 1023) / 1024;       // 98
    int t = threadIdx.x;
    int s0 = t * CH;
    int s1 = min(s0 + CH, NN);
    int s = 0;
    for (int i = s0; i < s1; i++) s += g_deg[i];
    part[t] = s;
    __syncthreads();
    // Hillis-Steele inclusive scan
    for (int off = 1; off < 1024; off <<= 1) {
        int v = (t >= off) ? part[t - off] : 0;
        __syncthreads();
        part[t] += v;
        __syncthreads();
    }
    int run = (t == 0) ? 0 : part[t - 1];
    for (int i = s0; i < s1; i++) {
        g_off[i] = run;
        g_cur[i] = run;
        run += g_deg[i];
    }
    if (t == 1023) g_off[NN] = part[1023];
}

__global__ void scatter_edges_kernel(const int* __restrict__ ei) {
    int e = blockIdx.x * blockDim.x + threadIdx.x;
    if (e < NE) {
        int s = ei[e];
        int d = ei[NE + e];
        s = min(max(s, 0), NN - 1);
        d = min(max(d, 0), NN - 1);
        int p = atomicAdd(&g_cur[d], 1);
        g_srcs[p] = s;
    }
}

// ---------------- fused SAGE layer ----------------
// SRC: 0 = external feat param, 1 = g_h1, 2 = g_h2
// DST: 0 = none (last layer), 1 = g_h1, 2 = g_h2   (relu'd next-layer input)
// out_pre[n][j] = h[n] @ Ws + mean_agg[n] @ Wn + b   (pre-activation, to d_out region)
template <int DOUT, int SRC, int DST>
__global__ void __launch_bounds__(LTH)
sage_layer_kernel(const float* __restrict__ hin_ext,
                  const float* __restrict__ Ws,
                  const float* __restrict__ Wn,
                  const float* __restrict__ bias,
                  float* __restrict__ out_pre) {
    __shared__ float sWs[64 * DOUT];
    __shared__ float sWn[64 * DOUT];
    __shared__ float shh[NPB * 64];
    __shared__ float sha[NPB * 64];

    // device-side scratch selection (array decay gives true device addresses)
    const float* hin = (SRC == 0) ? hin_ext : (SRC == 1 ? (const float*)g_h1 : (const float*)g_h2);
    float* hnext = (DST == 0) ? (float*)0 : (DST == 1 ? (float*)g_h1 : (float*)g_h2);

    int t = threadIdx.x;
    // cooperative W load (whole block)
    for (int i = t; i < 64 * DOUT; i += LTH) {
        sWs[i] = Ws[i];
        sWn[i] = Wn[i];
    }

    int base = blockIdx.x * NPB;
    int w = t >> 5;
    int lane = t & 31;

    // ---- phase 1: per-warp aggregation, 8 nodes per warp ----
    for (int i = 0; i < NPB / 4; i++) {
        int nb = w * (NPB / 4) + i;
        int n = base + nb;
        float2 acc = make_float2(0.f, 0.f);
        if (n < NN) {
            const float2* hrow = (const float2*)(hin + (size_t)n * 64);
            float2 own = hrow[lane];
            *(float2*)&shh[nb * 64 + 2 * lane] = own;
            int e0 = g_off[n], e1 = g_off[n + 1];
            for (int e = e0; e < e1; e++) {
                int s = g_srcs[e];               // broadcast load within warp
                const float2* srow = (const float2*)(hin + (size_t)s * 64);
                float2 v = srow[lane];
                acc.x += v.x;
                acc.y += v.y;
            }
            float sc = 1.0f / fmaxf((float)(e1 - e0), 1.0f);
            acc.x *= sc;
            acc.y *= sc;
        }
        *(float2*)&sha[nb * 64 + 2 * lane] = acc;
    }
    __syncthreads();

    // ---- phase 2: register-tiled dual matmul ----
    // thread t -> tj in [0,16), tn in [0,8). Handles nodes {tn + 8*i}, j = tj + 16*m.
    constexpr int MJ = DOUT / 16;   // 4 for DOUT=64, 1 for DOUT=16
    int tj = t & 15;
    int tn = t >> 4;

    float acc[4][MJ];
#pragma unroll
    for (int i = 0; i < 4; i++)
#pragma unroll
        for (int m = 0; m < MJ; m++)
            acc[i][m] = bias[tj + 16 * m];

#pragma unroll
    for (int k = 0; k < 64; k++) {
        float ws[MJ], wn[MJ];
#pragma unroll
        for (int m = 0; m < MJ; m++) {
            ws[m] = sWs[k * DOUT + tj + 16 * m];
            wn[m] = sWn[k * DOUT + tj + 16 * m];
        }
#pragma unroll
        for (int i = 0; i < 4; i++) {
            int nb = tn + 8 * i;
            float hk = shh[nb * 64 + k];
            float ak = sha[nb * 64 + k];
#pragma unroll
            for (int m = 0; m < MJ; m++)
                acc[i][m] = fmaf(hk, ws[m], fmaf(ak, wn[m], acc[i][m]));
        }
    }

    // ---- store ----
#pragma unroll
    for (int i = 0; i < 4; i++) {
        int nb = tn + 8 * i;
        int n = base + nb;
        if (n < NN) {
#pragma unroll
            for (int m = 0; m < MJ; m++) {
                int j = tj + 16 * m;
                float v = acc[i][m];
                out_pre[(size_t)n * DOUT + j] = v;
                if (DST != 0) hnext[(size_t)n * 64 + j] = fmaxf(v, 0.0f);
            }
        }
    }
}

// ---------------- launch ----------------
extern "C" void kernel_launch(void* const* d_in, const int* in_sizes, int n_in,
                              void* d_out, int out_size) {
    const float* feat = (const float*)d_in[0];
    const int*   ei   = (const int*)d_in[1];      // int32 (jax x64 disabled)
    const float* Ws0 = (const float*)d_in[2];
    const float* Wn0 = (const float*)d_in[3];
    const float* b0  = (const float*)d_in[4];
    const float* Ws1 = (const float*)d_in[5];
    const float* Wn1 = (const float*)d_in[6];
    const float* b1  = (const float*)d_in[7];
    const float* Ws2 = (const float*)d_in[8];
    const float* Wn2 = (const float*)d_in[9];
    const float* b2  = (const float*)d_in[10];

    float* out = (float*)d_out;
    // output layout: [ h (100000*16) | embed0 (100000*64) | embed1 (100000*64) ]
    float* out_h  = out;
    float* out_e0 = out + (size_t)NN * 16;
    float* out_e1 = out + (size_t)NN * 16 + (size_t)NN * 64;

    // CSR build
    zero_deg_kernel<<<(NN + 255) / 256, 256>>>();
    count_deg_kernel<<<(NE + 255) / 256, 256>>>(ei);
    scan_deg_kernel<<<1, 1024>>>();
    scatter_edges_kernel<<<(NE + 255) / 256, 256>>>(ei);

    int nblk = (NN + NPB - 1) / NPB;   // 3125
    // layer 0: feat -> embed0 (pre), g_h1 = relu
    sage_layer_kernel<64, 0, 1><<<nblk, LTH>>>(feat, Ws0, Wn0, b0, out_e0);
    // layer 1: g_h1 -> embed1 (pre), g_h2 = relu
    sage_layer_kernel<64, 1, 2><<<nblk, LTH>>>(nullptr, Ws1, Wn1, b1, out_e1);
    // layer 2: g_h2 -> h (final, no relu)
    sage_layer_kernel<16, 2, 0><<<nblk, LTH>>>(nullptr, Ws2, Wn2, b2, out_h);
}